// round 17
// baseline (speedup 1.0000x reference)
#include <cuda_runtime.h>
#include <cuda_bf16.h>

// Fused, cp.async ring-buffered gather (R16 theory, smem fixed: RING=9 ->
// 47.4KB static smem < 48KB limit).
// 256 thr = 8 warps, 4 rows/block, 2 warps/row, grid 512.
// Gather: per warp, entries stream through a 9-slot smem ring via
// cp.async.cg (16B/lane/entry, one commit group per entry). Steady state
// keeps 9 entries (4.5KB) in flight per warp continuously — no register cap.
// Then transpose s -> s4[f]={r0..r3} and lean packed-FFMA2 GEMM (R14).

#define RPB   4
#define NW    8
#define MJ    128
#define FE    64
#define FC    128
#define RING  9           // ring slots per warp (512B each)

#define CP_ASYNC_16(dst_u32, src_ptr) \
    asm volatile("cp.async.cg.shared.global [%0], [%1], 16;" \
                 :: "r"(dst_u32), "l"(src_ptr))
#define CP_COMMIT()   asm volatile("cp.async.commit_group;")
#define CP_WAIT(n)    asm volatile("cp.async.wait_group %0;" :: "n"(n))

__global__ __launch_bounds__(256, 4)
void gcn_fused_kernel(const float* __restrict__ sf1,
                      const float* __restrict__ sf2,
                      const float* __restrict__ adj,
                      const float* __restrict__ W,
                      const float* __restrict__ bias,
                      float* __restrict__ out)
{
    // ring buffer; re-used as red4 (8*4*32 float4 = 16KB) in the GEMM phase
    __shared__ __align__(16) unsigned char s_buf[NW * RING * 512];   // 36864 B
    __shared__ int    s_off[NW][68];
    __shared__ float  s_val[NW][68];
    __shared__ float  s_part[NW][FC];
    __shared__ float  s_degp[NW];
    __shared__ float4 s4[FC];

    const int t    = threadIdx.x;
    const int w    = t >> 5;
    const int lane = t & 31;
    const int pr   = w >> 1;
    const int h    = w & 1;
    const int row0 = blockIdx.x * RPB;
    const int row  = row0 + pr;

    // ---- Phase 1 (warp-local): compact 64 adj values ----
    const float* arow = adj + (size_t)row * MJ + h * 64;
    const float a0 = __ldg(arow + lane);
    const float a1 = __ldg(arow + lane + 32);
    const unsigned b0 = __ballot_sync(0xffffffffu, a0 != 0.0f);
    const unsigned b1 = __ballot_sync(0xffffffffu, a1 != 0.0f);
    const int c0  = __popc(b0);
    const int nnz = c0 + __popc(b1);
    const unsigned lm = (1u << lane) - 1u;
    if (a0 != 0.0f) { const int p = __popc(b0 & lm);
                      s_off[w][p] = (h * 64 + lane     ) * FE; s_val[w][p] = a0; }
    if (a1 != 0.0f) { const int p = c0 + __popc(b1 & lm);
                      s_off[w][p] = (h * 64 + lane + 32) * FE; s_val[w][p] = a1; }
    {
        float d = a0 + a1;
        #pragma unroll
        for (int off = 16; off > 0; off >>= 1)
            d += __shfl_down_sync(0xffffffffu, d, off);
        if (lane == 0) s_degp[w] = d;
    }
    __syncwarp();

    // ---- Phase 2: cp.async ring gather ----
    // lanes 0-15: sf1 (ch 0..63); lanes 16-31: sf2 (ch 64..127).
    {
        const float* base = ((lane < 16) ? sf1 : sf2)
                          + (size_t)row * MJ * FE + (lane & 15) * 4;
        const unsigned bufb =
            (unsigned)__cvta_generic_to_shared(s_buf) + (w * RING) * 512 + lane * 16;

        const int E = (nnz < RING) ? nnz : RING;
        for (int k = 0; k < E; ++k) {                     // fill
            CP_ASYNC_16(bufb + (unsigned)(k * 512), base + s_off[w][k]);
            CP_COMMIT();
        }

        float4 acc = make_float4(0.f, 0.f, 0.f, 0.f);
        int k = 0;
        for (; k + RING < nnz; ++k) {                     // steady state
            CP_WAIT(RING - 1);                            // entry k complete
            const float a = s_val[w][k];
            const float4 v = *reinterpret_cast<const float4*>(
                s_buf + (w * RING + (k % RING)) * 512 + lane * 16);
            acc.x += a * v.x; acc.y += a * v.y;
            acc.z += a * v.z; acc.w += a * v.w;
            CP_ASYNC_16(bufb + (unsigned)((k % RING) * 512),
                        base + s_off[w][k + RING]);       // refill same slot
            CP_COMMIT();
        }
        CP_WAIT(0);                                       // drain
        for (; k < nnz; ++k) {
            const float a = s_val[w][k];
            const float4 v = *reinterpret_cast<const float4*>(
                s_buf + (w * RING + (k % RING)) * 512 + lane * 16);
            acc.x += a * v.x; acc.y += a * v.y;
            acc.z += a * v.z; acc.w += a * v.w;
        }
        reinterpret_cast<float4*>(s_part[w])[lane] = acc;
    }
    __syncthreads();   // all gathers done; s_buf dead -> reusable

    // ---- Phase 3a: transpose+combine into s4[f] = {r0,r1,r2,r3} ----
    if (t < FC) {
        const int f = t;
        float4 v;
        v.x = s_part[0][f] + s_part[1][f];
        v.y = s_part[2][f] + s_part[3][f];
        v.z = s_part[4][f] + s_part[5][f];
        v.w = s_part[6][f] + s_part[7][f];
        s4[f] = v;
    }
    __syncthreads();

    float4* red4 = reinterpret_cast<float4*>(s_buf);      // [8][4][32]

    // ---- Phase 3b: lean GEMM (packed fma.rn.f32x2), f-slice 16 per warp ----
    {
        const int f0 = w * 16;
        const float4* W4 = reinterpret_cast<const float4*>(W);
        unsigned long long acc01[4] = {0ull, 0ull, 0ull, 0ull};
        unsigned long long acc23[4] = {0ull, 0ull, 0ull, 0ull};
        #pragma unroll
        for (int kk = 0; kk < 16; ++kk) {
            const int f = f0 + kk;
            unsigned long long s01, s23;
            asm volatile("ld.shared.v2.u64 {%0, %1}, [%2];"
                         : "=l"(s01), "=l"(s23)
                         : "r"((unsigned)__cvta_generic_to_shared(&s4[f])));
            const float4 wv = W4[f * 32 + lane];
            unsigned long long wd;
            asm("mov.b64 %0, {%1, %1};" : "=l"(wd) : "f"(wv.x));
            asm("fma.rn.f32x2 %0, %1, %2, %0;" : "+l"(acc01[0]) : "l"(s01), "l"(wd));
            asm("fma.rn.f32x2 %0, %1, %2, %0;" : "+l"(acc23[0]) : "l"(s23), "l"(wd));
            asm("mov.b64 %0, {%1, %1};" : "=l"(wd) : "f"(wv.y));
            asm("fma.rn.f32x2 %0, %1, %2, %0;" : "+l"(acc01[1]) : "l"(s01), "l"(wd));
            asm("fma.rn.f32x2 %0, %1, %2, %0;" : "+l"(acc23[1]) : "l"(s23), "l"(wd));
            asm("mov.b64 %0, {%1, %1};" : "=l"(wd) : "f"(wv.z));
            asm("fma.rn.f32x2 %0, %1, %2, %0;" : "+l"(acc01[2]) : "l"(s01), "l"(wd));
            asm("fma.rn.f32x2 %0, %1, %2, %0;" : "+l"(acc23[2]) : "l"(s23), "l"(wd));
            asm("mov.b64 %0, {%1, %1};" : "=l"(wd) : "f"(wv.w));
            asm("fma.rn.f32x2 %0, %1, %2, %0;" : "+l"(acc01[3]) : "l"(s01), "l"(wd));
            asm("fma.rn.f32x2 %0, %1, %2, %0;" : "+l"(acc23[3]) : "l"(s23), "l"(wd));
        }
        float4 r0v, r1v, r2v, r3v;
        asm("mov.b64 {%0, %1}, %2;" : "=f"(r0v.x), "=f"(r1v.x) : "l"(acc01[0]));
        asm("mov.b64 {%0, %1}, %2;" : "=f"(r0v.y), "=f"(r1v.y) : "l"(acc01[1]));
        asm("mov.b64 {%0, %1}, %2;" : "=f"(r0v.z), "=f"(r1v.z) : "l"(acc01[2]));
        asm("mov.b64 {%0, %1}, %2;" : "=f"(r0v.w), "=f"(r1v.w) : "l"(acc01[3]));
        asm("mov.b64 {%0, %1}, %2;" : "=f"(r2v.x), "=f"(r3v.x) : "l"(acc23[0]));
        asm("mov.b64 {%0, %1}, %2;" : "=f"(r2v.y), "=f"(r3v.y) : "l"(acc23[1]));
        asm("mov.b64 {%0, %1}, %2;" : "=f"(r2v.z), "=f"(r3v.z) : "l"(acc23[2]));
        asm("mov.b64 {%0, %1}, %2;" : "=f"(r2v.w), "=f"(r3v.w) : "l"(acc23[3]));
        red4[(w * 4 + 0) * 32 + lane] = r0v;
        red4[(w * 4 + 1) * 32 + lane] = r1v;
        red4[(w * 4 + 2) * 32 + lane] = r2v;
        red4[(w * 4 + 3) * 32 + lane] = r3v;
    }
    __syncthreads();

    // ---- Phase 4: combine 8 f-slices + bias*deg + relu + store ----
    if (t < 128) {
        const int r = t >> 5, q = t & 31;
        float4 rs = red4[(0 * 4 + r) * 32 + q];
        #pragma unroll
        for (int sl = 1; sl < 8; ++sl) {
            const float4 p = red4[(sl * 4 + r) * 32 + q];
            rs.x += p.x; rs.y += p.y; rs.z += p.z; rs.w += p.w;
        }
        const float4 bb = reinterpret_cast<const float4*>(bias)[q];
        const float  d  = s_degp[2 * r] + s_degp[2 * r + 1];
        float4 o4;
        o4.x = fmaxf(rs.x + bb.x * d, 0.0f);
        o4.y = fmaxf(rs.y + bb.y * d, 0.0f);
        o4.z = fmaxf(rs.z + bb.z * d, 0.0f);
        o4.w = fmaxf(rs.w + bb.w * d, 0.0f);
        reinterpret_cast<float4*>(out)[(size_t)(row0 + r) * 32 + q] = o4;
    }
}

extern "C" void kernel_launch(void* const* d_in, const int* in_sizes, int n_in,
                              void* d_out, int out_size)
{
    const float* sf1  = (const float*)d_in[0];  // (16,128,128,64)
    const float* sf2  = (const float*)d_in[1];  // (16,128,128,64)
    const float* adj  = (const float*)d_in[2];  // (16,128,128)
    const float* W    = (const float*)d_in[3];  // (128,128)
    const float* bias = (const float*)d_in[4];  // (128,)
    float* out = (float*)d_out;                 // (16,128,128)

    gcn_fused_kernel<<<2048 / RPB, 256>>>(sf1, sf2, adj, W, bias, out);
}